// round 8
// baseline (speedup 1.0000x reference)
#include <cuda_runtime.h>
#include <cuda_bf16.h>
#include <cstdint>

// Sliding-window causal attention, fp32, no 1/sqrt(d) scaling.
// B=2, H=12, S=2048, D=64, W=256. Mask analytic: j in (i-W, i].
// v8: pre-pass converts K/V -> bf16 hi/lo global scratch (once, not 5x);
//     main kernel cp.asyncs bf16 straight to smem (no cvt, no staging regs),
//     4 CTAs/SM, fine-grained MMA tile skipping at window edges.

#define DH   64
#define WIN  256
#define SEQ  2048
#define BM   64
#define BN   32
#define NT   128
#define KST  72                        // smem row stride in halves (144 B)
#define BUFB (BN * KST * 2)            // bytes per array per buffer (4608)

#define NROW (2 * 12 * SEQ)            // 49152 rows total
#define N4G  (NROW * DH / 8)           // uint4 (8 dims) per array = 393216

// 25.2 MB of pre-converted bf16 scratch (hi/lo for K and V), [row][dim] packed.
__device__ uint4 KhG[N4G], KlG[N4G], VhG[N4G], VlG[N4G];

__device__ __forceinline__ uint32_t packbf(float hi, float lo) {
    uint32_t d; asm("cvt.rn.bf16x2.f32 %0, %1, %2;" : "=r"(d) : "f"(hi), "f"(lo));
    return d;
}
__device__ __forceinline__ float hi_f(uint32_t r) { return __uint_as_float(r & 0xffff0000u); }
__device__ __forceinline__ float lo_f(uint32_t r) { return __uint_as_float(r << 16); }

__device__ __forceinline__ void mma16816(float* c,
    uint32_t a0, uint32_t a1, uint32_t a2, uint32_t a3,
    uint32_t b0, uint32_t b1)
{
    asm("mma.sync.aligned.m16n8k16.row.col.f32.bf16.bf16.f32 "
        "{%0,%1,%2,%3}, {%4,%5,%6,%7}, {%8,%9}, {%0,%1,%2,%3};"
        : "+f"(c[0]), "+f"(c[1]), "+f"(c[2]), "+f"(c[3])
        : "r"(a0), "r"(a1), "r"(a2), "r"(a3), "r"(b0), "r"(b1));
}
__device__ __forceinline__ void ldsm4(uint32_t* r, uint32_t a) {
    asm volatile("ldmatrix.sync.aligned.m8n8.x4.shared.b16 {%0,%1,%2,%3}, [%4];"
        : "=r"(r[0]), "=r"(r[1]), "=r"(r[2]), "=r"(r[3]) : "r"(a));
}
__device__ __forceinline__ void ldsm4t(uint32_t* r, uint32_t a) {
    asm volatile("ldmatrix.sync.aligned.m8n8.x4.trans.shared.b16 {%0,%1,%2,%3}, [%4];"
        : "=r"(r[0]), "=r"(r[1]), "=r"(r[2]), "=r"(r[3]) : "r"(a));
}
__device__ __forceinline__ void cp16(uint32_t dst, const void* src) {
    asm volatile("cp.async.cg.shared.global [%0], [%1], 16;" :: "r"(dst), "l"(src));
}

// ---------------- pre-pass: fp32 -> bf16 hi/lo ----------------
__global__ __launch_bounds__(256) void conv_kv(
    const float* __restrict__ k, const float* __restrict__ v)
{
    const int idx = blockIdx.x * 256 + threadIdx.x;    // < N4G
    const float4* kp = (const float4*)k;
    const float4* vp = (const float4*)v;

    float4 a = kp[2 * idx], b = kp[2 * idx + 1];
    uint32_t h0 = packbf(a.y, a.x), h1 = packbf(a.w, a.z);
    uint32_t h2 = packbf(b.y, b.x), h3 = packbf(b.w, b.z);
    KhG[idx] = make_uint4(h0, h1, h2, h3);
    KlG[idx] = make_uint4(
        packbf(a.y - hi_f(h0), a.x - lo_f(h0)),
        packbf(a.w - hi_f(h1), a.z - lo_f(h1)),
        packbf(b.y - hi_f(h2), b.x - lo_f(h2)),
        packbf(b.w - hi_f(h3), b.z - lo_f(h3)));

    a = vp[2 * idx]; b = vp[2 * idx + 1];
    h0 = packbf(a.y, a.x); h1 = packbf(a.w, a.z);
    h2 = packbf(b.y, b.x); h3 = packbf(b.w, b.z);
    VhG[idx] = make_uint4(h0, h1, h2, h3);
    VlG[idx] = make_uint4(
        packbf(a.y - hi_f(h0), a.x - lo_f(h0)),
        packbf(a.w - hi_f(h1), a.z - lo_f(h1)),
        packbf(b.y - hi_f(h2), b.x - lo_f(h2)),
        packbf(b.w - hi_f(h3), b.z - lo_f(h3)));
}

// ---------------- main attention kernel ----------------
__global__ __launch_bounds__(NT, 4) void swa_mma8(
    const float* __restrict__ q,
    float* __restrict__ out)
{
    __shared__ __align__(16) uint16_t Kh[2][BN * KST];
    __shared__ __align__(16) uint16_t Klo[2][BN * KST];
    __shared__ __align__(16) uint16_t Vh[2][BN * KST];
    __shared__ __align__(16) uint16_t Vlo[2][BN * KST];

    const int t    = threadIdx.x;
    const int lane = t & 31;
    const int wid  = t >> 5;
    const int g    = lane >> 2;
    const int tg   = lane & 3;
    const int i0   = blockIdx.x * BM;
    const int w0   = i0 + wid * 16;
    const int rowA = w0 + g;
    const int rowB = rowA + 8;
    const int bh   = blockIdx.y;
    const size_t base    = (size_t)bh * SEQ * DH;   // fp32 element base (q/out)
    const int    baseRow = bh * SEQ;                // row base for scratch

    // chunk-invariant ldmatrix lane bases (buffer 0; add buf*BUFB)
    const uint32_t khB = (uint32_t)__cvta_generic_to_shared(&Kh[0][0])
                       + ((lane & 7) * KST + (lane >> 3) * 8) * 2;
    const uint32_t klB = (uint32_t)__cvta_generic_to_shared(&Klo[0][0])
                       + ((lane & 7) * KST + (lane >> 3) * 8) * 2;
    const uint32_t vhB = (uint32_t)__cvta_generic_to_shared(&Vh[0][0])
                       + (((lane & 7) + ((lane >> 3) & 1) * 8) * KST) * 2
                       + (lane >> 4) * 16;
    const uint32_t vlB = (uint32_t)__cvta_generic_to_shared(&Vlo[0][0])
                       + (((lane & 7) + ((lane >> 3) & 1) * 8) * KST) * 2
                       + (lane >> 4) * 16;

    // loader: thread covers rows r0 and r0+16, 16B col slot (t&7), all 4 arrays
    const int r0   = t >> 3;            // 0..15
    const int colb = (t & 7) * 16;      // byte col within 128B row
    const uint32_t dKh = (uint32_t)__cvta_generic_to_shared(&Kh[0][0]) + r0 * 144 + colb;
    const uint32_t dKl = (uint32_t)__cvta_generic_to_shared(&Klo[0][0]) + r0 * 144 + colb;
    const uint32_t dVh = (uint32_t)__cvta_generic_to_shared(&Vh[0][0]) + r0 * 144 + colb;
    const uint32_t dVl = (uint32_t)__cvta_generic_to_shared(&Vlo[0][0]) + r0 * 144 + colb;

    // ---- Q fragments (hi/lo), loaded once ----
    uint32_t qh[4][4], ql[4][4];
    {
        const float* qp = q + base;
        #pragma unroll
        for (int kd = 0; kd < 4; kd++) {
            const int d0 = kd * 16 + tg * 2;
            const float xA0 = qp[(size_t)rowA * DH + d0];
            const float xA1 = qp[(size_t)rowA * DH + d0 + 1];
            const float xB0 = qp[(size_t)rowB * DH + d0];
            const float xB1 = qp[(size_t)rowB * DH + d0 + 1];
            const float yA0 = qp[(size_t)rowA * DH + d0 + 8];
            const float yA1 = qp[(size_t)rowA * DH + d0 + 9];
            const float yB0 = qp[(size_t)rowB * DH + d0 + 8];
            const float yB1 = qp[(size_t)rowB * DH + d0 + 9];
            qh[kd][0] = packbf(xA1, xA0);
            qh[kd][1] = packbf(xB1, xB0);
            qh[kd][2] = packbf(yA1, yA0);
            qh[kd][3] = packbf(yB1, yB0);
            ql[kd][0] = packbf(xA1 - hi_f(qh[kd][0]), xA0 - lo_f(qh[kd][0]));
            ql[kd][1] = packbf(xB1 - hi_f(qh[kd][1]), xB0 - lo_f(qh[kd][1]));
            ql[kd][2] = packbf(yA1 - hi_f(qh[kd][2]), yA0 - lo_f(qh[kd][2]));
            ql[kd][3] = packbf(yB1 - hi_f(qh[kd][3]), yB0 - lo_f(qh[kd][3]));
        }
    }

    float o[8][4];
    #pragma unroll
    for (int m = 0; m < 8; m++) { o[m][0]=0.f; o[m][1]=0.f; o[m][2]=0.f; o[m][3]=0.f; }
    float lsum0 = 0.f, lsum1 = 0.f;

    int js = i0 - WIN + 1;
    if (js < 0) js = 0;
    js &= ~(BN - 1);
    const int nch = (i0 + BM - js) / BN;   // >= 2 always

    // issue chunk c into buf (c&1): 8 x cp.async.16
    auto issue = [&](int c) {
        const uint32_t bo = (uint32_t)(c & 1) * BUFB;
        const size_t so = (size_t)(baseRow + js + c * BN + r0) * 128 + colb;
        const char* pkh = (const char*)KhG + so;
        const char* pkl = (const char*)KlG + so;
        const char* pvh = (const char*)VhG + so;
        const char* pvl = (const char*)VlG + so;
        cp16(dKh + bo, pkh);           cp16(dKh + bo + 2304, pkh + 2048);
        cp16(dKl + bo, pkl);           cp16(dKl + bo + 2304, pkl + 2048);
        cp16(dVh + bo, pvh);           cp16(dVh + bo + 2304, pvh + 2048);
        cp16(dVl + bo, pvl);           cp16(dVl + bo + 2304, pvl + 2048);
        asm volatile("cp.async.commit_group;");
    };

    issue(0);
    issue(1);

    for (int c = 0; c < nch; c++) {
        const int j0 = js + c * BN;
        const uint32_t bo = (uint32_t)(c & 1) * BUFB;

        if (c + 1 < nch) asm volatile("cp.async.wait_group 1;");
        else             asm volatile("cp.async.wait_group 0;");
        __syncthreads();

        // warp-uniform chunk guard
        if (j0 <= w0 + 15 && j0 + BN - 1 >= w0 - WIN + 1) {
            // ---- S = Q K^T : per-8-key tile skip ----
            float s[4][4];
            #pragma unroll
            for (int nt = 0; nt < 4; nt++) { s[nt][0]=0.f; s[nt][1]=0.f; s[nt][2]=0.f; s[nt][3]=0.f; }

            #pragma unroll
            for (int nt = 0; nt < 4; nt++) {
                const int jt = j0 + nt * 8;
                if (jt <= w0 + 15 && jt + 7 >= w0 - WIN + 1) {
                    #pragma unroll
                    for (int kd2 = 0; kd2 < 2; kd2++) {
                        uint32_t bhh[4], bll[4];
                        const uint32_t off = bo + (uint32_t)(nt * 8 * KST * 2 + kd2 * 64);
                        ldsm4(bhh, khB + off);
                        ldsm4(bll, klB + off);
                        const int k0 = 2 * kd2, k1 = 2 * kd2 + 1;
                        mma16816(s[nt], qh[k0][0], qh[k0][1], qh[k0][2], qh[k0][3], bhh[0], bhh[1]);
                        mma16816(s[nt], qh[k1][0], qh[k1][1], qh[k1][2], qh[k1][3], bhh[2], bhh[3]);
                        mma16816(s[nt], qh[k0][0], qh[k0][1], qh[k0][2], qh[k0][3], bll[0], bll[1]);
                        mma16816(s[nt], qh[k1][0], qh[k1][1], qh[k1][2], qh[k1][3], bll[2], bll[3]);
                        mma16816(s[nt], ql[k0][0], ql[k0][1], ql[k0][2], ql[k0][3], bhh[0], bhh[1]);
                        mma16816(s[nt], ql[k1][0], ql[k1][1], ql[k1][2], ql[k1][3], bhh[2], bhh[3]);
                    }
                }
            }

            // ---- mask + exp + row sums ----
            #pragma unroll
            for (int nt = 0; nt < 4; nt++) {
                const int jc = j0 + nt * 8 + tg * 2;
                const float p00 = ((unsigned)(rowA - jc)       < (unsigned)WIN) ? __expf(s[nt][0]) : 0.f;
                const float p01 = ((unsigned)(rowA - (jc + 1)) < (unsigned)WIN) ? __expf(s[nt][1]) : 0.f;
                const float p10 = ((unsigned)(rowB - jc)       < (unsigned)WIN) ? __expf(s[nt][2]) : 0.f;
                const float p11 = ((unsigned)(rowB - (jc + 1)) < (unsigned)WIN) ? __expf(s[nt][3]) : 0.f;
                lsum0 += p00 + p01;
                lsum1 += p10 + p11;
                s[nt][0] = p00; s[nt][1] = p01; s[nt][2] = p10; s[nt][3] = p11;
            }

            // ---- O += P V : per-16-key half skip ----
            #pragma unroll
            for (int ks = 0; ks < 2; ks++) {
                const int jt = j0 + ks * 16;
                if (jt <= w0 + 15 && jt + 15 >= w0 - WIN + 1) {
                    const float* pa = s[2 * ks];
                    const float* pb = s[2 * ks + 1];
                    uint32_t aH[4], aL[4];
                    aH[0] = packbf(pa[1], pa[0]);
                    aH[1] = packbf(pa[3], pa[2]);
                    aH[2] = packbf(pb[1], pb[0]);
                    aH[3] = packbf(pb[3], pb[2]);
                    aL[0] = packbf(pa[1] - hi_f(aH[0]), pa[0] - lo_f(aH[0]));
                    aL[1] = packbf(pa[3] - hi_f(aH[1]), pa[2] - lo_f(aH[1]));
                    aL[2] = packbf(pb[1] - hi_f(aH[2]), pb[0] - lo_f(aH[2]));
                    aL[3] = packbf(pb[3] - hi_f(aH[3]), pb[2] - lo_f(aH[3]));

                    #pragma unroll
                    for (int mt2 = 0; mt2 < 4; mt2++) {
                        uint32_t bhh[4], bll[4];
                        const uint32_t off = bo + (uint32_t)(ks * 16 * KST * 2 + mt2 * 32);
                        ldsm4t(bhh, vhB + off);
                        ldsm4t(bll, vlB + off);
                        const int m0 = 2 * mt2, m1 = 2 * mt2 + 1;
                        mma16816(o[m0], aH[0], aH[1], aH[2], aH[3], bhh[0], bhh[1]);
                        mma16816(o[m1], aH[0], aH[1], aH[2], aH[3], bhh[2], bhh[3]);
                        mma16816(o[m0], aH[0], aH[1], aH[2], aH[3], bll[0], bll[1]);
                        mma16816(o[m1], aH[0], aH[1], aH[2], aH[3], bll[2], bll[3]);
                        mma16816(o[m0], aL[0], aL[1], aL[2], aL[3], bhh[0], bhh[1]);
                        mma16816(o[m1], aL[0], aL[1], aL[2], aL[3], bhh[2], bhh[3]);
                    }
                }
            }
        }

        __syncthreads();                 // readers done before buf reuse
        if (c + 2 < nch) issue(c + 2);   // lands during next iter's compute
    }

    // ---- finalize ----
    lsum0 += __shfl_xor_sync(0xffffffffu, lsum0, 1);
    lsum0 += __shfl_xor_sync(0xffffffffu, lsum0, 2);
    lsum1 += __shfl_xor_sync(0xffffffffu, lsum1, 1);
    lsum1 += __shfl_xor_sync(0xffffffffu, lsum1, 2);
    const float ia = 1.f / lsum0;
    const float ib = 1.f / lsum1;

    float* op = out + base;
    #pragma unroll
    for (int mt = 0; mt < 8; mt++) {
        const int d0 = mt * 8 + tg * 2;
        *(float2*)&op[(size_t)rowA * DH + d0] = make_float2(o[mt][0] * ia, o[mt][1] * ia);
        *(float2*)&op[(size_t)rowB * DH + d0] = make_float2(o[mt][2] * ib, o[mt][3] * ib);
    }
}

extern "C" void kernel_launch(void* const* d_in, const int* in_sizes, int n_in,
                              void* d_out, int out_size)
{
    const float* q = (const float*)d_in[0];
    const float* k = (const float*)d_in[1];
    const float* v = (const float*)d_in[2];
    // d_in[3] = mask (analytic, unused)
    float* out = (float*)d_out;

    conv_kv<<<N4G / 256, 256>>>(k, v);

    dim3 grid(SEQ / BM, 2 * 12);   // 32 x 24
    dim3 block(NT);
    swa_mma8<<<grid, block>>>(q, out);
}